// round 11
// baseline (speedup 1.0000x reference)
#include <cuda_runtime.h>
#include <cuda_bf16.h>
#include <math_constants.h>

// Problem constants (fixed by the reference)
#define BB     2
#define HH     112
#define WW     112
#define HW     (HH * WW)        // 12544
#define NPIX   (BB * HW)        // 25088
#define SEG_T  0.7f
#define EPS_K  1e-7f
// Output nonzero requires q <= eps - ln(0.7) = 0.3566750.
#define Q_RAD  0.36f
#define Q_CUT  0.37f

// 7x7 tiles of 16x16 per image; 98 blocks; 1024 threads = one per region pt.
#define TILE   16
#define TPS    7
#define HALO   8                 // R<=8 <=> maxvar<=88.9 <=> |v|<=9.43
#define REG    32                // TILE + 2*HALO
#define NTHR   1024              // REG*REG region points, 1 per thread
#define NWARP  32

__global__ void __launch_bounds__(NTHR, 1)
k_one(const float* __restrict__ variance,
      const float* __restrict__ center,
      float* __restrict__ out, int out_size)
{
    __shared__ unsigned int qmin[TILE * TILE];
    // Worklist; f0/f1/f2 hold vx/vy/v2 after compaction, then A/B2/C after
    // the coefficient phase (each thread rewrites its own slot; syncs between
    // cross-thread reads).
    __shared__ float wl_f0[NTHR], wl_f1[NTHR], wl_f2[NTHR];
    __shared__ int   wl_pr[NTHR], wl_pc[NTHR];   // tile-local point coords
    __shared__ int   wl_rm[NTHR];                // (R<<16) | magic_m
    __shared__ int   wl_cnt;

    const int tid = threadIdx.x;
    if (tid < TILE * TILE) qmin[tid] = 0x7F800000u;   // +inf
    if (tid == 0) wl_cnt = 0;

    const int blk = blockIdx.x;
    const int b   = blk / (TPS * TPS);
    const int t   = blk - b * (TPS * TPS);
    const int tr  = (t / TPS) * TILE;
    const int tc  = (t % TPS) * TILE;

    const float* varb = variance + (size_t)b * 3 * HW;
    const float* cenb = center   + (size_t)b * HW;

    // ---- Phase A: one region point per thread; 4 independent loads up front.
    const int lr = tid >> 5;
    const int lc = tid & 31;
    const int pr = tr - HALO + lr;
    const int pc = tc - HALO + lc;
    const bool inb = (pr >= 0) & (pr < HH) & (pc >= 0) & (pc < WW);

    float vx = 0.0f, vy = 0.0f, v2 = 0.0f;
    if (inb) {
        int pix = pr * WW + pc;
        float cm  = cenb[pix];
        float a0  = varb[pix];
        float a1  = varb[HW + pix];
        float a2  = varb[2 * HW + pix];
        float mask = (cm > SEG_T) ? 1.0f : 0.0f;
        vx = a0 * mask;
        vy = a1 * mask;
        v2 = a2;
    }
    // sel = (vx + vy) != 0  (matches torch.nonzero(vx+vy) semantics)
    const bool sel = inb && ((vx + vy) != 0.0f);

    __syncthreads();   // qmin + wl_cnt initialized

    // ---- Phase B: warp-aggregated compaction of selected points.
    {
        unsigned m = __ballot_sync(0xFFFFFFFFu, sel);
        if (m) {
            int lane   = tid & 31;
            int leader = __ffs(m) - 1;
            int base   = 0;
            if (lane == leader) base = atomicAdd(&wl_cnt, __popc(m));
            base = __shfl_sync(0xFFFFFFFFu, base, leader);
            if (sel) {
                int slot = base + __popc(m & ((1u << lane) - 1u));
                wl_f0[slot] = vx;
                wl_f1[slot] = vy;
                wl_f2[slot] = v2;
                wl_pr[slot] = pr - tr;   // tile-local (range [-8, 23])
                wl_pc[slot] = pc - tc;
            }
        }
    }
    __syncthreads();
    const int cnt = wl_cnt;

    // ---- Phase C1: dense coefficient math (threads < cnt, packed warps).
    // Math order identical to the validated R2 kernel.
    if (tid < cnt) {
        float pvx = wl_f0[tid], pvy = wl_f1[tid], pv2 = wl_f2[tid];

        float theta = 3.14f * (1.0f / (1.0f + expf(-pv2)));
        float s, c;
        sincosf(theta, &s, &c);

        float var_x = pvx * pvx + EPS_K;
        float var_y = pvy * pvy + EPS_K;

        float inv2x = 1.0f / (2.0f * var_x);
        float inv2y = 1.0f / (2.0f * var_y);

        float A  = c * c * inv2x + s * s * inv2y;
        float C  = s * s * inv2x + c * c * inv2y;
        float B2 = 2.0f * (-2.0f * s * c / (4.0f * var_x)
                           + 2.0f * s * c / (4.0f * var_y));

        // q >= d^2/(2*maxvar): nonzero output needs q <= 0.3567
        float maxvar = fmaxf(var_x, var_y);
        int R = (int)floorf(sqrtf(2.0f * maxvar * Q_RAD)) + 1;   // <= HALO

        int w = 2 * R + 1;               // 3..17
        int m = 65536 / w + 1;           // exact cell/w for cell < 289

        wl_f0[tid] = A;
        wl_f1[tid] = B2;
        wl_f2[tid] = C;
        wl_rm[tid] = (R << 16) | m;
    }
    __syncthreads();

    // ---- Phase C2: warp-cooperative scatter. Warp wp handles points
    // wp, wp+32, ...; lanes cover the (2R+1)^2 box cells in parallel.
    {
        const int wp   = tid >> 5;
        const int lane = tid & 31;
        for (int p = wp; p < cnt; p += NWARP) {
            float A   = wl_f0[p];          // smem broadcast reads
            float B2  = wl_f1[p];
            float C   = wl_f2[p];
            int   rm  = wl_rm[p];
            int   lpr = wl_pr[p];
            int   lpc = wl_pc[p];
            int   R   = rm >> 16;
            int   m   = rm & 0xFFFF;
            int   w   = 2 * R + 1;
            int   cells = w * w;

            for (int cell = lane; cell < cells; cell += 32) {
                int dy = (cell * m) >> 16;       // cell / w (exact)
                int dx = cell - dy * w;
                int i  = lpr + dy - R;
                int j  = lpc + dx - R;
                if ((unsigned)i < (unsigned)TILE &&
                    (unsigned)j < (unsigned)TILE) {
                    float di  = (float)(dy - R);
                    float dj  = (float)(dx - R);
                    float adi = A * di * di;     // same op order as R2 kernel
                    float bdi = B2 * di;
                    float q   = fmaf(C * dj + bdi, dj, adi);
                    if (q <= Q_CUT) {
                        atomicMin(&qmin[i * TILE + j], __float_as_uint(q));
                    }
                }
            }
        }
    }
    __syncthreads();

    // ---- Phase D: finalize this tile (threads 0..255 own one pixel each).
    if (tid < TILE * TILE) {
        int oy = tid >> 4;
        int ox = tid & (TILE - 1);
        float q = __uint_as_float(qmin[tid]);
        float g = expf(-q + EPS_K);            // q=+inf -> g=0
        out[(size_t)b * HW + (tr + oy) * WW + (tc + ox)] =
            (g >= 0.7f) ? g : 0.0f;
    }

    // Zero-fill any trailing output elements (the `flag` scalar).
    if (blk == 0 && tid == 0) {
        for (int o = NPIX; o < out_size; ++o) out[o] = 0.0f;
    }
}

// ---------------------------------------------------------------------------
// Inputs (metadata order): x[2,32,112,112], variance[2,3,112,112],
// center_map[2,1,112,112], conv_w[1,32], conv_b[1].
// x / conv_w / conv_b are dead in the reference (threshold branch unused).
// ---------------------------------------------------------------------------
extern "C" void kernel_launch(void* const* d_in, const int* in_sizes, int n_in,
                              void* d_out, int out_size)
{
    const float* variance = (const float*)d_in[1];
    const float* center   = (const float*)d_in[2];
    float*       out      = (float*)d_out;

    k_one<<<BB * TPS * TPS, NTHR>>>(variance, center, out, out_size);
}